// round 1
// baseline (speedup 1.0000x reference)
#include <cuda_runtime.h>
#include <math.h>

// Problem constants
#define BB 4
#define TT 512
#define DD 192
#define CHK 16
#define NC (TT/CHK)        // 32 chunks per batch
#define NBC (BB*NC)        // 128 chunk-blocks total
#define PAD 196            // smem row pitch (floats), 16B-aligned, kills stride-192 bank conflicts

// ---------------- scratch (module-static device memory; no allocations) ----------------
__device__ float g_Q[BB*TT*DD];
__device__ float g_K[BB*TT*DD];
__device__ float g_V[BB*TT*DD];
__device__ float g_G  [(size_t)NBC*DD*DD];   // per-chunk K^T V
__device__ float g_Sst[(size_t)NBC*DD*DD];   // exclusive prefix state (+S0)
__device__ float g_z  [(size_t)NBC*DD];      // per-chunk sum of K rows
__device__ float g_zst[(size_t)NBC*DD];      // exclusive prefix (+Z0)

__device__ __forceinline__ float elu1(float v) {
    return v > 0.f ? v + 1.f : expf(v);
}

// ---------------- Kernel 1: qkv = x @ W^T + b, elu+1 on Q,K; scatter to g_Q/g_K/g_V ----
// M=2048, N=576, K=192. 64x64 block tile, 256 threads, 4x4 microtile (strided).
__global__ __launch_bounds__(256) void qkv_kernel(const float* __restrict__ x,
                                                  const float* __restrict__ W,
                                                  const float* __restrict__ bias) {
    extern __shared__ float sm[];
    float* Xs = sm;                 // [64][PAD]
    float* Ws = sm + 64*PAD;        // [64][PAD]
    const int tid = threadIdx.x;
    const int m0 = blockIdx.x * 64;
    const int n0 = blockIdx.y * 64;

    for (int idx = tid; idx < 64*48; idx += 256) {
        int r = idx / 48, c4 = (idx % 48) * 4;
        *reinterpret_cast<float4*>(Xs + r*PAD + c4) =
            *reinterpret_cast<const float4*>(x + (size_t)(m0 + r)*DD + c4);
        *reinterpret_cast<float4*>(Ws + r*PAD + c4) =
            *reinterpret_cast<const float4*>(W + (size_t)(n0 + r)*DD + c4);
    }
    __syncthreads();

    const int tx = tid & 15;   // n lane
    const int ty = tid >> 4;   // m lane
    float acc[4][4];
    #pragma unroll
    for (int v = 0; v < 4; v++)
        #pragma unroll
        for (int u = 0; u < 4; u++) acc[v][u] = 0.f;

    for (int k = 0; k < DD; k++) {
        float a[4], w[4];
        #pragma unroll
        for (int v = 0; v < 4; v++) a[v] = Xs[(ty + 16*v)*PAD + k];
        #pragma unroll
        for (int u = 0; u < 4; u++) w[u] = Ws[(tx + 16*u)*PAD + k];
        #pragma unroll
        for (int v = 0; v < 4; v++)
            #pragma unroll
            for (int u = 0; u < 4; u++) acc[v][u] += a[v]*w[u];
    }

    #pragma unroll
    for (int v = 0; v < 4; v++) {
        int m = m0 + ty + 16*v;
        #pragma unroll
        for (int u = 0; u < 4; u++) {
            int n = n0 + tx + 16*u;
            float val = acc[v][u] + bias[n];
            if (n < DD)            g_Q[(size_t)m*DD + n]        = elu1(val);
            else if (n < 2*DD)     g_K[(size_t)m*DD + (n-DD)]   = elu1(val);
            else                   g_V[(size_t)m*DD + (n-2*DD)] = val;
        }
    }
}

// ---------------- Kernel 2: per-chunk G = K^T V (192x192, inner 16) and z = sum K -------
__global__ __launch_bounds__(256) void chunk_kernel() {
    __shared__ float Ks[CHK*PAD];
    __shared__ float Vs[CHK*PAD];
    const int tid = threadIdx.x;
    const int b = blockIdx.x / NC, c = blockIdx.x % NC;
    const size_t tbase = ((size_t)b*TT + (size_t)c*CHK) * DD;

    for (int idx = tid; idx < CHK*48; idx += 256) {
        int r = idx / 48, c4 = (idx % 48) * 4;
        *reinterpret_cast<float4*>(Ks + r*PAD + c4) =
            *reinterpret_cast<const float4*>(g_K + tbase + (size_t)r*DD + c4);
        *reinterpret_cast<float4*>(Vs + r*PAD + c4) =
            *reinterpret_cast<const float4*>(g_V + tbase + (size_t)r*DD + c4);
    }
    __syncthreads();

    if (tid < DD) {
        float zs = 0.f;
        #pragma unroll
        for (int s = 0; s < CHK; s++) zs += Ks[s*PAD + tid];
        g_z[((size_t)b*NC + c)*DD + tid] = zs;
    }

    const int tx = tid & 15, ty = tid >> 4;
    float acc[12][12];
    #pragma unroll
    for (int a = 0; a < 12; a++)
        #pragma unroll
        for (int e = 0; e < 12; e++) acc[a][e] = 0.f;

    #pragma unroll
    for (int s = 0; s < CHK; s++) {
        float ki[12], vj[12];
        #pragma unroll
        for (int a = 0; a < 12; a++) ki[a] = Ks[s*PAD + ty + 16*a];
        #pragma unroll
        for (int e = 0; e < 12; e++) vj[e] = Vs[s*PAD + tx + 16*e];
        #pragma unroll
        for (int a = 0; a < 12; a++)
            #pragma unroll
            for (int e = 0; e < 12; e++) acc[a][e] += ki[a]*vj[e];
    }

    float* Gp = g_G + ((size_t)b*NC + c)*(size_t)(DD*DD);
    #pragma unroll
    for (int a = 0; a < 12; a++)
        #pragma unroll
        for (int e = 0; e < 12; e++)
            Gp[(size_t)(ty + 16*a)*DD + tx + 16*e] = acc[a][e];
}

// ---------------- Kernel 3: exclusive prefix over chunks for S; emits S_last ------------
__global__ __launch_bounds__(256) void prefixS_kernel(const float* __restrict__ S0,
                                                      float* __restrict__ outS) {
    int e = blockIdx.x * 256 + threadIdx.x;          // e < B*D*D = 147456
    int b = e / (DD*DD), r = e - b*(DD*DD);
    float run = S0[e];
    size_t base = (size_t)b*NC*DD*DD + r;
    #pragma unroll
    for (int c = 0; c < NC; c++) {
        g_Sst[base + (size_t)c*DD*DD] = run;
        run += g_G[base + (size_t)c*DD*DD];
    }
    outS[e] = run;   // = S0 + full sum = S[:, -1]  (clip @1e20 never binds)
}

// ---------------- Kernel 3b: exclusive prefix for z; emits Z_last -----------------------
__global__ __launch_bounds__(256) void prefixZ_kernel(const float* __restrict__ Z0,
                                                      float* __restrict__ outZ) {
    int e = blockIdx.x * 256 + threadIdx.x;
    if (e >= BB*DD) return;
    int b = e / DD, i = e - b*DD;
    float run = Z0[e];
    size_t base = (size_t)b*NC*DD + i;
    #pragma unroll
    for (int c = 0; c < NC; c++) {
        g_zst[base + (size_t)c*DD] = run;
        run += g_z[base + (size_t)c*DD];
    }
    outZ[e] = run;
}

// ---------------- Kernel 4: per-chunk output -------------------------------------------
// out[t] = (Q[t]^T S_start + (masked QK^T) V) / (Q[t].z_start + rowsum(masked A) + 1e-5)
__global__ __launch_bounds__(256) void out_kernel(float* __restrict__ out) {
    extern __shared__ float sm[];
    float* Qs   = sm;                 // [16][PAD]
    float* KVs  = sm + CHK*PAD;       // [16][PAD]  K then reused for V
    float* As   = sm + 2*CHK*PAD;     // [16][16]
    float* dens = As + 256;           // [16]
    float* Pan  = dens + 16;          // 2 x [16][192]  S-state panel double buffer

    const int tid = threadIdx.x;
    const int b = blockIdx.x / NC, c = blockIdx.x % NC;
    const size_t tbase = ((size_t)b*TT + (size_t)c*CHK) * DD;

    for (int idx = tid; idx < CHK*48; idx += 256) {
        int r = idx / 48, c4 = (idx % 48) * 4;
        *reinterpret_cast<float4*>(Qs  + r*PAD + c4) =
            *reinterpret_cast<const float4*>(g_Q + tbase + (size_t)r*DD + c4);
        *reinterpret_cast<float4*>(KVs + r*PAD + c4) =
            *reinterpret_cast<const float4*>(g_K + tbase + (size_t)r*DD + c4);
    }
    __syncthreads();

    // scores A[t][s] = Q[t].K[s], s<=t, else 0 — one entry per thread
    {
        int t_ = tid >> 4, s_ = tid & 15;
        float a = 0.f;
        if (s_ <= t_) {
            for (int k = 0; k < DD; k++) a += Qs[t_*PAD + k] * KVs[s_*PAD + k];
        }
        As[t_*16 + s_] = a;
    }
    __syncthreads();

    // denominators
    if (tid < CHK) {
        const float* zp = g_zst + ((size_t)b*NC + c)*DD;
        float ds = 0.f;
        for (int k = 0; k < DD; k++) ds += Qs[tid*PAD + k] * zp[k];
        #pragma unroll
        for (int s = 0; s < CHK; s++) ds += As[tid*16 + s];
        dens[tid] = ds + 1e-5f;
    }
    __syncthreads();

    // V replaces K in smem
    for (int idx = tid; idx < CHK*48; idx += 256) {
        int r = idx / 48, c4 = (idx % 48) * 4;
        *reinterpret_cast<float4*>(KVs + r*PAD + c4) =
            *reinterpret_cast<const float4*>(g_V + tbase + (size_t)r*DD + c4);
    }
    __syncthreads();

    const int tj = tid & 63;     // j in {tj, tj+64, tj+128}
    const int tt = tid >> 6;     // t in {4*tt .. 4*tt+3}
    float acc[4][3];
    #pragma unroll
    for (int r = 0; r < 4; r++)
        #pragma unroll
        for (int u = 0; u < 3; u++) acc[r][u] = 0.f;

    // intra-chunk: masked A @ V
    #pragma unroll
    for (int s = 0; s < CHK; s++) {
        float av[4], vv[3];
        #pragma unroll
        for (int r = 0; r < 4; r++) av[r] = As[(4*tt + r)*16 + s];
        #pragma unroll
        for (int u = 0; u < 3; u++) vv[u] = KVs[s*PAD + tj + 64*u];
        #pragma unroll
        for (int r = 0; r < 4; r++)
            #pragma unroll
            for (int u = 0; u < 3; u++) acc[r][u] += av[r]*vv[u];
    }

    // inter-chunk: Q @ S_start, streamed in 12 panels of 16 i-rows, double buffered
    const float* Sp = g_Sst + ((size_t)b*NC + c)*(size_t)(DD*DD);
    float4 rg[3];
    #pragma unroll
    for (int q = 0; q < 3; q++)
        rg[q] = *reinterpret_cast<const float4*>(Sp + (size_t)(tid + 256*q)*4);

    for (int p = 0; p < 12; p++) {
        float* buf = Pan + (p & 1) * 3072;
        __syncthreads();   // prior readers of this buffer (iter p-2) are done
        #pragma unroll
        for (int q = 0; q < 3; q++)
            *reinterpret_cast<float4*>(buf + (size_t)(tid + 256*q)*4) = rg[q];
        if (p < 11) {
            const float* src = Sp + (size_t)(p + 1)*3072;
            #pragma unroll
            for (int q = 0; q < 3; q++)
                rg[q] = *reinterpret_cast<const float4*>(src + (size_t)(tid + 256*q)*4);
        }
        __syncthreads();
        #pragma unroll
        for (int i = 0; i < 16; i++) {
            float qv[4], sv[3];
            #pragma unroll
            for (int r = 0; r < 4; r++) qv[r] = Qs[(4*tt + r)*PAD + p*16 + i];
            #pragma unroll
            for (int u = 0; u < 3; u++) sv[u] = buf[i*192 + tj + 64*u];
            #pragma unroll
            for (int r = 0; r < 4; r++)
                #pragma unroll
                for (int u = 0; u < 3; u++) acc[r][u] += qv[r]*sv[u];
        }
    }

    #pragma unroll
    for (int r = 0; r < 4; r++) {
        int t = 4*tt + r;
        float dv = dens[t];
        #pragma unroll
        for (int u = 0; u < 3; u++)
            out[tbase + (size_t)t*DD + tj + 64*u] = acc[r][u] / dv;
    }
}

// ---------------- launch ----------------------------------------------------------------
extern "C" void kernel_launch(void* const* d_in, const int* in_sizes, int n_in,
                              void* d_out, int out_size) {
    const float* x  = (const float*)d_in[0];
    const float* W  = (const float*)d_in[1];
    const float* bi = (const float*)d_in[2];
    const float* S0 = (const float*)d_in[3];
    const float* Z0 = (const float*)d_in[4];
    float* out = (float*)d_out;

    const int SM1 = 2*64*PAD*4;                       // 100352 B
    const int SM4 = (2*CHK*PAD + 256 + 16 + 2*3072)*4; // 50752 B
    cudaFuncSetAttribute(qkv_kernel, cudaFuncAttributeMaxDynamicSharedMemorySize, SM1);
    cudaFuncSetAttribute(out_kernel, cudaFuncAttributeMaxDynamicSharedMemorySize, SM4);

    qkv_kernel<<<dim3(32, 9), 256, SM1>>>(x, W, bi);
    chunk_kernel<<<NBC, 256>>>();
    prefixS_kernel<<<(BB*DD*DD)/256, 256>>>(S0, out + (size_t)BB*TT*DD);
    prefixZ_kernel<<<3, 256>>>(Z0, out + (size_t)BB*TT*DD + (size_t)BB*DD*DD);
    out_kernel<<<NBC, 256, SM4>>>(out);
}

// round 5
// speedup vs baseline: 1.3310x; 1.3310x over previous
#include <cuda_runtime.h>
#include <math.h>

// Problem constants
#define BB 4
#define TT 512
#define DD 192
#define CHK 16
#define NC (TT/CHK)        // 32 chunks per batch
#define NBC (BB*NC)        // 128 chunk-blocks total
#define PAD 196            // smem row pitch (floats), 16B-aligned, kills stride-192 bank conflicts

// ---------------- scratch (module-static device memory; no allocations) ----------------
__device__ float g_Q[BB*TT*DD];
__device__ float g_K[BB*TT*DD];
__device__ float g_V[BB*TT*DD];
__device__ float g_G  [(size_t)NBC*DD*DD];   // per-chunk K^T V
__device__ float g_Sst[(size_t)NBC*DD*DD];   // exclusive prefix state (+S0)
__device__ float g_z  [(size_t)NBC*DD];      // per-chunk sum of K rows
__device__ float g_zst[(size_t)NBC*DD];      // exclusive prefix (+Z0)

__device__ __forceinline__ float elu1(float v) {
    return v > 0.f ? v + 1.f : expf(v);
}

// ---------------- Kernel 1: qkv = x @ W^T + b, elu+1 on Q,K; scatter to g_Q/g_K/g_V ----
// M=2048, N=576, K=192. 64x64 block tile, 256 threads, 4x4 microtile (strided).
__global__ __launch_bounds__(256) void qkv_kernel(const float* __restrict__ x,
                                                  const float* __restrict__ W,
                                                  const float* __restrict__ bias) {
    extern __shared__ float sm[];
    float* Xs = sm;                 // [64][PAD]
    float* Ws = sm + 64*PAD;        // [64][PAD]
    const int tid = threadIdx.x;
    const int m0 = blockIdx.x * 64;
    const int n0 = blockIdx.y * 64;

    for (int idx = tid; idx < 64*48; idx += 256) {
        int r = idx / 48, c4 = (idx % 48) * 4;
        *reinterpret_cast<float4*>(Xs + r*PAD + c4) =
            *reinterpret_cast<const float4*>(x + (size_t)(m0 + r)*DD + c4);
        *reinterpret_cast<float4*>(Ws + r*PAD + c4) =
            *reinterpret_cast<const float4*>(W + (size_t)(n0 + r)*DD + c4);
    }
    __syncthreads();

    const int tx = tid & 15;   // n lane
    const int ty = tid >> 4;   // m lane
    float acc[4][4];
    #pragma unroll
    for (int v = 0; v < 4; v++)
        #pragma unroll
        for (int u = 0; u < 4; u++) acc[v][u] = 0.f;

    for (int k = 0; k < DD; k++) {
        float a[4], w[4];
        #pragma unroll
        for (int v = 0; v < 4; v++) a[v] = Xs[(ty + 16*v)*PAD + k];
        #pragma unroll
        for (int u = 0; u < 4; u++) w[u] = Ws[(tx + 16*u)*PAD + k];
        #pragma unroll
        for (int v = 0; v < 4; v++)
            #pragma unroll
            for (int u = 0; u < 4; u++) acc[v][u] += a[v]*w[u];
    }

    #pragma unroll
    for (int v = 0; v < 4; v++) {
        int m = m0 + ty + 16*v;
        #pragma unroll
        for (int u = 0; u < 4; u++) {
            int n = n0 + tx + 16*u;
            float val = acc[v][u] + bias[n];
            if (n < DD)            g_Q[(size_t)m*DD + n]        = elu1(val);
            else if (n < 2*DD)     g_K[(size_t)m*DD + (n-DD)]   = elu1(val);
            else                   g_V[(size_t)m*DD + (n-2*DD)] = val;
        }
    }
}

// ---------------- Kernel 2: per-chunk G = K^T V (192x192, inner 16) and z = sum K -------
__global__ __launch_bounds__(256) void chunk_kernel() {
    __shared__ float Ks[CHK*PAD];
    __shared__ float Vs[CHK*PAD];
    const int tid = threadIdx.x;
    const int b = blockIdx.x / NC, c = blockIdx.x % NC;
    const size_t tbase = ((size_t)b*TT + (size_t)c*CHK) * DD;

    for (int idx = tid; idx < CHK*48; idx += 256) {
        int r = idx / 48, c4 = (idx % 48) * 4;
        *reinterpret_cast<float4*>(Ks + r*PAD + c4) =
            *reinterpret_cast<const float4*>(g_K + tbase + (size_t)r*DD + c4);
        *reinterpret_cast<float4*>(Vs + r*PAD + c4) =
            *reinterpret_cast<const float4*>(g_V + tbase + (size_t)r*DD + c4);
    }
    __syncthreads();

    if (tid < DD) {
        float zs = 0.f;
        #pragma unroll
        for (int s = 0; s < CHK; s++) zs += Ks[s*PAD + tid];
        g_z[((size_t)b*NC + c)*DD + tid] = zs;
    }

    const int tx = tid & 15, ty = tid >> 4;
    float acc[12][12];
    #pragma unroll
    for (int a = 0; a < 12; a++)
        #pragma unroll
        for (int e = 0; e < 12; e++) acc[a][e] = 0.f;

    #pragma unroll
    for (int s = 0; s < CHK; s++) {
        float ki[12], vj[12];
        #pragma unroll
        for (int a = 0; a < 12; a++) ki[a] = Ks[s*PAD + ty + 16*a];
        #pragma unroll
        for (int e = 0; e < 12; e++) vj[e] = Vs[s*PAD + tx + 16*e];
        #pragma unroll
        for (int a = 0; a < 12; a++)
            #pragma unroll
            for (int e = 0; e < 12; e++) acc[a][e] += ki[a]*vj[e];
    }

    float* Gp = g_G + ((size_t)b*NC + c)*(size_t)(DD*DD);
    #pragma unroll
    for (int a = 0; a < 12; a++)
        #pragma unroll
        for (int e = 0; e < 12; e++)
            Gp[(size_t)(ty + 16*a)*DD + tx + 16*e] = acc[a][e];
}

// ---------------- Kernel 3: fused exclusive prefix over chunks (S and z) ----------------
// Blocks [0, 576): S path, one thread per (b, r) element of the 192x192 state.
// Blocks [576, 579): z path, one thread per (b, i).
// Loads are batched into a register array (MLP=32) so only ONE ~577-cycle DRAM
// latency is exposed per thread instead of 32 serial ones.
__global__ __launch_bounds__(256) void prefix_kernel(const float* __restrict__ S0,
                                                     const float* __restrict__ Z0,
                                                     float* __restrict__ outS,
                                                     float* __restrict__ outZ) {
    const int tid = threadIdx.x;
    if (blockIdx.x < 576) {
        int e = blockIdx.x * 256 + tid;              // e < B*D*D = 147456
        int b = e / (DD*DD), r = e - b*(DD*DD);
        size_t base = (size_t)b*NC*DD*DD + r;
        float v[NC];
        #pragma unroll
        for (int c = 0; c < NC; c++) v[c] = g_G[base + (size_t)c*DD*DD];
        float run = S0[e];
        #pragma unroll
        for (int c = 0; c < NC; c++) { float nv = run + v[c]; v[c] = run; run = nv; }
        #pragma unroll
        for (int c = 0; c < NC; c++) g_Sst[base + (size_t)c*DD*DD] = v[c];
        outS[e] = run;   // = S0 + full sum = S[:, -1]  (clip @1e20 never binds)
    } else {
        int e = (blockIdx.x - 576) * 256 + tid;
        if (e >= BB*DD) return;
        int b = e / DD, i = e - b*DD;
        size_t base = (size_t)b*NC*DD + i;
        float v[NC];
        #pragma unroll
        for (int c = 0; c < NC; c++) v[c] = g_z[base + (size_t)c*DD];
        float run = Z0[e];
        #pragma unroll
        for (int c = 0; c < NC; c++) { float nv = run + v[c]; v[c] = run; run = nv; }
        #pragma unroll
        for (int c = 0; c < NC; c++) g_zst[base + (size_t)c*DD] = v[c];
        outZ[e] = run;
    }
}

// ---------------- Kernel 4: per-chunk output -------------------------------------------
// out[t] = (Q[t]^T S_start + (masked QK^T) V) / (Q[t].z_start + rowsum(masked A) + 1e-5)
__global__ __launch_bounds__(256) void out_kernel(float* __restrict__ out) {
    extern __shared__ float sm[];
    float* Qs   = sm;                 // [16][PAD]
    float* KVs  = sm + CHK*PAD;       // [16][PAD]  K then reused for V
    float* As   = sm + 2*CHK*PAD;     // [16][16]
    float* dens = As + 256;           // [16]
    float* Pan  = dens + 16;          // 2 x [16][192]  S-state panel double buffer

    const int tid = threadIdx.x;
    const int b = blockIdx.x / NC, c = blockIdx.x % NC;
    const size_t tbase = ((size_t)b*TT + (size_t)c*CHK) * DD;

    for (int idx = tid; idx < CHK*48; idx += 256) {
        int r = idx / 48, c4 = (idx % 48) * 4;
        *reinterpret_cast<float4*>(Qs  + r*PAD + c4) =
            *reinterpret_cast<const float4*>(g_Q + tbase + (size_t)r*DD + c4);
        *reinterpret_cast<float4*>(KVs + r*PAD + c4) =
            *reinterpret_cast<const float4*>(g_K + tbase + (size_t)r*DD + c4);
    }
    __syncthreads();

    // scores A[t][s] = Q[t].K[s], s<=t, else 0 — one entry per thread
    {
        int t_ = tid >> 4, s_ = tid & 15;
        float a = 0.f;
        if (s_ <= t_) {
            for (int k = 0; k < DD; k++) a += Qs[t_*PAD + k] * KVs[s_*PAD + k];
        }
        As[t_*16 + s_] = a;
    }
    __syncthreads();

    // denominators
    if (tid < CHK) {
        const float* zp = g_zst + ((size_t)b*NC + c)*DD;
        float ds = 0.f;
        for (int k = 0; k < DD; k++) ds += Qs[tid*PAD + k] * zp[k];
        #pragma unroll
        for (int s = 0; s < CHK; s++) ds += As[tid*16 + s];
        dens[tid] = ds + 1e-5f;
    }
    __syncthreads();

    // V replaces K in smem
    for (int idx = tid; idx < CHK*48; idx += 256) {
        int r = idx / 48, c4 = (idx % 48) * 4;
        *reinterpret_cast<float4*>(KVs + r*PAD + c4) =
            *reinterpret_cast<const float4*>(g_V + tbase + (size_t)r*DD + c4);
    }
    __syncthreads();

    const int tj = tid & 63;     // j in {tj, tj+64, tj+128}
    const int tt = tid >> 6;     // t in {4*tt .. 4*tt+3}
    float acc[4][3];
    #pragma unroll
    for (int r = 0; r < 4; r++)
        #pragma unroll
        for (int u = 0; u < 3; u++) acc[r][u] = 0.f;

    // intra-chunk: masked A @ V
    #pragma unroll
    for (int s = 0; s < CHK; s++) {
        float av[4], vv[3];
        #pragma unroll
        for (int r = 0; r < 4; r++) av[r] = As[(4*tt + r)*16 + s];
        #pragma unroll
        for (int u = 0; u < 3; u++) vv[u] = KVs[s*PAD + tj + 64*u];
        #pragma unroll
        for (int r = 0; r < 4; r++)
            #pragma unroll
            for (int u = 0; u < 3; u++) acc[r][u] += av[r]*vv[u];
    }

    // inter-chunk: Q @ S_start, streamed in 12 panels of 16 i-rows, double buffered
    const float* Sp = g_Sst + ((size_t)b*NC + c)*(size_t)(DD*DD);
    float4 rg[3];
    #pragma unroll
    for (int q = 0; q < 3; q++)
        rg[q] = *reinterpret_cast<const float4*>(Sp + (size_t)(tid + 256*q)*4);

    for (int p = 0; p < 12; p++) {
        float* buf = Pan + (p & 1) * 3072;
        __syncthreads();   // prior readers of this buffer (iter p-2) are done
        #pragma unroll
        for (int q = 0; q < 3; q++)
            *reinterpret_cast<float4*>(buf + (size_t)(tid + 256*q)*4) = rg[q];
        if (p < 11) {
            const float* src = Sp + (size_t)(p + 1)*3072;
            #pragma unroll
            for (int q = 0; q < 3; q++)
                rg[q] = *reinterpret_cast<const float4*>(src + (size_t)(tid + 256*q)*4);
        }
        __syncthreads();
        #pragma unroll
        for (int i = 0; i < 16; i++) {
            float qv[4], sv[3];
            #pragma unroll
            for (int r = 0; r < 4; r++) qv[r] = Qs[(4*tt + r)*PAD + p*16 + i];
            #pragma unroll
            for (int u = 0; u < 3; u++) sv[u] = buf[i*192 + tj + 64*u];
            #pragma unroll
            for (int r = 0; r < 4; r++)
                #pragma unroll
                for (int u = 0; u < 3; u++) acc[r][u] += qv[r]*sv[u];
        }
    }

    #pragma unroll
    for (int r = 0; r < 4; r++) {
        int t = 4*tt + r;
        float dv = dens[t];
        #pragma unroll
        for (int u = 0; u < 3; u++)
            out[tbase + (size_t)t*DD + tj + 64*u] = acc[r][u] / dv;
    }
}

// ---------------- launch ----------------------------------------------------------------
extern "C" void kernel_launch(void* const* d_in, const int* in_sizes, int n_in,
                              void* d_out, int out_size) {
    const float* x  = (const float*)d_in[0];
    const float* W  = (const float*)d_in[1];
    const float* bi = (const float*)d_in[2];
    const float* S0 = (const float*)d_in[3];
    const float* Z0 = (const float*)d_in[4];
    float* out = (float*)d_out;

    const int SM1 = 2*64*PAD*4;                        // 100352 B
    const int SM4 = (2*CHK*PAD + 256 + 16 + 2*3072)*4; // 50752 B
    cudaFuncSetAttribute(qkv_kernel, cudaFuncAttributeMaxDynamicSharedMemorySize, SM1);
    cudaFuncSetAttribute(out_kernel, cudaFuncAttributeMaxDynamicSharedMemorySize, SM4);

    qkv_kernel<<<dim3(32, 9), 256, SM1>>>(x, W, bi);
    chunk_kernel<<<NBC, 256>>>();
    prefix_kernel<<<579, 256>>>(S0, Z0,
                                out + (size_t)BB*TT*DD,
                                out + (size_t)BB*TT*DD + (size_t)BB*DD*DD);
    out_kernel<<<NBC, 256, SM4>>>(out);
}